// round 9
// baseline (speedup 1.0000x reference)
#include <cuda_runtime.h>
#include <cstddef>

#define WORDS   1000000
#define EMB_D   64
#define KTH     4
#define BATCH   8192

#define E_ELEMS   ((long)WORDS * EMB_D)          // 64,000,000
#define B_ELEMS   ((long)WORDS * KTH)            // 4,000,000
#define TOT_ELEMS (E_ELEMS + B_ELEMS)            // 68,000,000
#define K_CH      (TOT_ELEMS / 4)                // 17,000,000 float4 chunks
#define E_CH      (E_ELEMS / 4)                  // 16,000,000
#define RB        128                            // reduce blocks
#define INVB      (1.0f / (float)BATCH)

#define TPB     256
#define UNROLL  4
#define CPB     (TPB * UNROLL)                   // 1024 chunks per block

// Per-block partials (fully overwritten each launch -> graph-replay safe).
__device__ float g_pw[RB][EMB_D];
__device__ float g_pb[RB][KTH];
__device__ int   g_pc[RB];
// Last-block ticket. Reset to 0 by the last block every launch -> replay safe.
__device__ unsigned int g_ticket;

// ---------------------------------------------------------------------------
// Helpers
// ---------------------------------------------------------------------------
__device__ __forceinline__ float load_src(long s,
                                          const float* __restrict__ emb,
                                          const float* __restrict__ bia) {
    return (s < E_ELEMS) ? __ldg(emb + s) : __ldg(bia + (s - E_ELEMS));
}

__device__ __forceinline__ float4 load_chunk_cs(long k,
                                                const float* __restrict__ emb,
                                                const float* __restrict__ bia) {
    const float4* p = (k < E_CH)
        ? (reinterpret_cast<const float4*>(emb) + k)
        : (reinterpret_cast<const float4*>(bia) + (k - E_CH));
    return __ldcs(p);
}

// ---------------------------------------------------------------------------
// Reduce body (runs inside main kernel for blockIdx.x < RB)
// ---------------------------------------------------------------------------
__device__ void reduce_body(const float* __restrict__ embed,
                            const float* __restrict__ bias,
                            const int*   __restrict__ ctx_id,
                            const int*   __restrict__ tgt,
                            const int*   __restrict__ lab) {
    __shared__ float s_ctx[EMB_D];
    __shared__ float s_bias[KTH];
    __shared__ float s_w[8][EMB_D];
    __shared__ float s_b[8][KTH];
    __shared__ int   s_c[8];

    const int tid = threadIdx.x;
    const int ctx = __ldg(ctx_id);
    if (tid < EMB_D) s_ctx[tid]  = __ldg(embed + (size_t)ctx * EMB_D + tid);
    if (tid < KTH)   s_bias[tid] = __ldg(bias  + (size_t)ctx * KTH + tid);
    __syncthreads();

    const int warp  = tid >> 5;
    const int lane  = tid & 31;
    const int gwarp = blockIdx.x * 8 + warp;     // 1024 warps total
    const int twarps = RB * 8;

    const float2 c2 = reinterpret_cast<const float2*>(s_ctx)[lane];

    float wx = 0.0f, wy = 0.0f;
    float b0 = 0.0f, b1 = 0.0f, b2 = 0.0f, b3 = 0.0f;
    int corr = 0;

    for (int b = gwarp; b < BATCH; b += twarps) {
        const int t = __ldg(tgt + b);
        const float2 e2 =
            reinterpret_cast<const float2*>(embed + (size_t)t * EMB_D)[lane];
        float p = e2.x * c2.x + e2.y * c2.y;
        #pragma unroll
        for (int o = 16; o; o >>= 1) p += __shfl_xor_sync(0xffffffffu, p, o);
        const float dot = p;

        const int   L    = __ldg(lab + b);
        const float labf = (float)L;

        float taurow = 0.0f;
        int   plabel = KTH + 1;
        float tj[KTH];
        #pragma unroll
        for (int j = KTH - 1; j >= 0; j--) {
            const float db = dot - s_bias[j];
            if (db <= 0.0f) plabel = j + 1;
            const float yt  = (j < L) ? 1.0f : -1.0f;
            const float tau = (db * yt > 0.0f) ? 0.0f : labf;
            tj[j] = tau;
            taurow += tau;
        }
        if (lane == 0) {
            b0 += tj[0]; b1 += tj[1]; b2 += tj[2]; b3 += tj[3];
            if (plabel == L) corr++;
        }
        wx += taurow * e2.x;
        wy += taurow * e2.y;
    }

    s_w[warp][2 * lane]     = wx;
    s_w[warp][2 * lane + 1] = wy;
    if (lane == 0) {
        s_b[warp][0] = b0; s_b[warp][1] = b1; s_b[warp][2] = b2; s_b[warp][3] = b3;
        s_c[warp] = corr;
    }
    __syncthreads();

    if (tid < EMB_D) {
        float s = 0.0f;
        #pragma unroll
        for (int w = 0; w < 8; w++) s += s_w[w][tid];
        g_pw[blockIdx.x][tid] = s;
    }
    if (tid < KTH) {
        float s = 0.0f;
        #pragma unroll
        for (int w = 0; w < 8; w++) s += s_b[w][tid];
        g_pb[blockIdx.x][tid] = s;
    }
    if (tid == 0) {
        int s = 0;
        #pragma unroll
        for (int w = 0; w < 8; w++) s += s_c[w];
        g_pc[blockIdx.x] = s;
    }
}

// ---------------------------------------------------------------------------
// Patch body: executed by the LAST block to finish. Reduces per-block
// partials (L2-resident) and writes acc + ctx rows + head + tail.
// ---------------------------------------------------------------------------
__device__ void patch_body(const float* __restrict__ emb,
                           const float* __restrict__ bia,
                           const int*   __restrict__ ctx_id,
                           float* __restrict__ out) {
    __shared__ float t_w[4][EMB_D];
    __shared__ float s_w[EMB_D];
    __shared__ float s_pb[4][KTH];
    __shared__ int   s_pc[4];
    __shared__ float s_b[KTH];
    __shared__ int   s_c;

    const int tid  = threadIdx.x;
    const int lane = tid & 31;
    const int warp = tid >> 5;

    // g_pw: 128x64. Group g = tid>>6 accumulates rows g, g+4, ... (coalesced).
    {
        const int g = tid >> 6;
        const int c = tid & 63;
        float acc = 0.0f;
        #pragma unroll
        for (int i = 0; i < RB / 4; i++)
            acc += g_pw[g + 4 * i][c];
        t_w[g][c] = acc;
    }

    // g_pb: 128x4 rows as float4 + shuffle reduce; g_pc alongside.
    if (tid < 128) {
        float4 v = reinterpret_cast<const float4*>(g_pb)[tid];
        int c = g_pc[tid];
        #pragma unroll
        for (int o = 16; o; o >>= 1) {
            v.x += __shfl_xor_sync(0xffffffffu, v.x, o);
            v.y += __shfl_xor_sync(0xffffffffu, v.y, o);
            v.z += __shfl_xor_sync(0xffffffffu, v.z, o);
            v.w += __shfl_xor_sync(0xffffffffu, v.w, o);
            c   += __shfl_xor_sync(0xffffffffu, c, o);
        }
        if (lane == 0) {
            s_pb[warp][0] = v.x; s_pb[warp][1] = v.y;
            s_pb[warp][2] = v.z; s_pb[warp][3] = v.w;
            s_pc[warp] = c;
        }
    }
    __syncthreads();

    if (tid < EMB_D)
        s_w[tid] = t_w[0][tid] + t_w[1][tid] + t_w[2][tid] + t_w[3][tid];
    if (tid >= 64 && tid < 64 + KTH) {
        const int j = tid - 64;
        s_b[j] = s_pb[0][j] + s_pb[1][j] + s_pb[2][j] + s_pb[3][j];
    }
    if (tid == 128)
        s_c = s_pc[0] + s_pc[1] + s_pc[2] + s_pc[3];
    __syncthreads();

    const int  ctx   = __ldg(ctx_id);
    const long wbase = (long)ctx * EMB_D;
    const long bbase = E_ELEMS + (long)ctx * KTH;

    if (tid == 128) out[0] = (float)s_c * INVB;

    // Context embed row (absolute value, not RMW; covers head if ctx==0).
    if (tid < EMB_D)
        out[1 + wbase + tid] = __ldg(emb + wbase + tid) + s_w[tid] * INVB;

    // Context bias row (covers tail if ctx == WORDS-1).
    if (tid >= 64 && tid < 64 + KTH) {
        const int j = tid - 64;
        out[1 + bbase + j] = __ldg(bia + (long)ctx * KTH + j) - s_b[j] * INVB;
    }

    // Head out[1..3]: chunk 0 never written by the copy.
    if (tid >= 129 && tid < 132 && ctx != 0) {
        const int j = tid - 129;
        out[1 + j] = __ldg(emb + j);
    }
    // Tail out[TOT].
    if (tid == 132 && ctx != WORDS - 1)
        out[TOT_ELEMS] = __ldg(bia + B_ELEMS - 1);
}

// ---------------------------------------------------------------------------
// Single fused kernel: reduce (blocks < RB) -> stream shifted copy (all) ->
// last block patches.
// ---------------------------------------------------------------------------
__global__ void __launch_bounds__(TPB)
prank_main_kernel(const float* __restrict__ emb,
                  const float* __restrict__ bia,
                  const int*   __restrict__ ctx_id,
                  const int*   __restrict__ tgt,
                  const int*   __restrict__ lab,
                  float* __restrict__ out,
                  unsigned int nblocks) {
    if (blockIdx.x < RB)
        reduce_body(emb, bia, ctx_id, tgt, lab);

    const long base = (long)blockIdx.x * CPB + 1;
    const int  tid  = threadIdx.x;
    const int  lane = tid & 31;

    long   k[UNROLL];
    float4 B[UNROLL];
    float  prev[UNROLL];

    #pragma unroll
    for (int i = 0; i < UNROLL; i++) {
        long kk = base + (long)i * TPB + tid;
        if (kk >= K_CH) kk = K_CH - 1;            // clamp keeps warp converged
        k[i] = kk;
        B[i] = load_chunk_cs(kk, emb, bia);
    }

    #pragma unroll
    for (int i = 0; i < UNROLL; i++) {
        prev[i] = __shfl_up_sync(0xffffffffu, B[i].w, 1);
        if (lane == 0) prev[i] = load_src(4 * k[i] - 1, emb, bia);
    }

    #pragma unroll
    for (int i = 0; i < UNROLL; i++) {
        const long kk = base + (long)i * TPB + tid;
        if (kk < K_CH) {
            __stcs(reinterpret_cast<float4*>(out) + kk,
                   make_float4(prev[i], B[i].x, B[i].y, B[i].z));
        }
    }

    // --- last-block-done: the final block runs the patch inline ---
    __shared__ unsigned int s_last;
    __threadfence();                               // make stores visible
    __syncthreads();                               // all threads' stores issued
    if (tid == 0) {
        const unsigned int old = atomicAdd(&g_ticket, 1u);
        s_last = (old == nblocks - 1u) ? 1u : 0u;
        if (s_last) g_ticket = 0;                  // reset -> graph-replay safe
    }
    __syncthreads();

    if (s_last) {
        __threadfence();                           // acquire other blocks' data
        patch_body(emb, bia, ctx_id, out);
    }
}

extern "C" void kernel_launch(void* const* d_in, const int* in_sizes, int n_in,
                              void* d_out, int out_size) {
    const float* in_embed = (const float*)d_in[0];
    const float* in_bias  = (const float*)d_in[1];
    const int*   ctx_id   = (const int*)d_in[2];
    const int*   tgt      = (const int*)d_in[3];
    const int*   lab      = (const int*)d_in[4];
    float* out = (float*)d_out;
    (void)n_in; (void)out_size; (void)in_sizes;

    const long nchunks = K_CH - 1;                       // chunks 1..K_CH-1
    const int  blocks  = (int)((nchunks + CPB - 1) / CPB);
    prank_main_kernel<<<blocks, TPB>>>(in_embed, in_bias, ctx_id, tgt, lab, out,
                                       (unsigned int)blocks);
}

// round 13
// speedup vs baseline: 1.0726x; 1.0726x over previous
#include <cuda_runtime.h>
#include <cstddef>

#define WORDS   1000000
#define EMB_D   64
#define KTH     4
#define BATCH   8192

#define E_ELEMS   ((long)WORDS * EMB_D)          // 64,000,000
#define B_ELEMS   ((long)WORDS * KTH)            // 4,000,000
#define TOT_ELEMS (E_ELEMS + B_ELEMS)            // 68,000,000
#define K_CH      (TOT_ELEMS / 4)                // 17,000,000 float4 chunks
#define E_CH      (E_ELEMS / 4)                  // 16,000,000
#define RB        128                            // reduce blocks
#define INVB      (1.0f / (float)BATCH)

#define TPB     256
#define UNROLL  4
#define CPB     (TPB * UNROLL)                   // 1024 chunks per block

// Per-block partials (fully overwritten each launch -> graph-replay safe).
__device__ float g_pw[RB][EMB_D];
__device__ float g_pb[RB][KTH];
__device__ int   g_pc[RB];
// Reduce-completion ticket (only RB blocks touch it; last one resets -> replay safe).
__device__ unsigned int g_ticket;

// ---------------------------------------------------------------------------
// Helpers
// ---------------------------------------------------------------------------
__device__ __forceinline__ float load_src(long s,
                                          const float* __restrict__ emb,
                                          const float* __restrict__ bia) {
    return (s < E_ELEMS) ? __ldg(emb + s) : __ldg(bia + (s - E_ELEMS));
}

__device__ __forceinline__ float4 load_chunk_cs(long k,
                                                const float* __restrict__ emb,
                                                const float* __restrict__ bia) {
    const float4* p = (k < E_CH)
        ? (reinterpret_cast<const float4*>(emb) + k)
        : (reinterpret_cast<const float4*>(bia) + (k - E_CH));
    return __ldcs(p);
}

// ---------------------------------------------------------------------------
// Reduce body (blocks 0..RB-1)
// ---------------------------------------------------------------------------
__device__ void reduce_body(const float* __restrict__ embed,
                            const float* __restrict__ bias,
                            const int*   __restrict__ ctx_id,
                            const int*   __restrict__ tgt,
                            const int*   __restrict__ lab) {
    __shared__ float s_ctx[EMB_D];
    __shared__ float s_bias[KTH];
    __shared__ float s_w[8][EMB_D];
    __shared__ float s_b[8][KTH];
    __shared__ int   s_c[8];

    const int tid = threadIdx.x;
    const int ctx = __ldg(ctx_id);
    if (tid < EMB_D) s_ctx[tid]  = __ldg(embed + (size_t)ctx * EMB_D + tid);
    if (tid < KTH)   s_bias[tid] = __ldg(bias  + (size_t)ctx * KTH + tid);
    __syncthreads();

    const int warp  = tid >> 5;
    const int lane  = tid & 31;
    const int gwarp = blockIdx.x * 8 + warp;     // 1024 warps total
    const int twarps = RB * 8;

    const float2 c2 = reinterpret_cast<const float2*>(s_ctx)[lane];

    float wx = 0.0f, wy = 0.0f;
    float b0 = 0.0f, b1 = 0.0f, b2 = 0.0f, b3 = 0.0f;
    int corr = 0;

    for (int b = gwarp; b < BATCH; b += twarps) {
        const int t = __ldg(tgt + b);
        const float2 e2 =
            reinterpret_cast<const float2*>(embed + (size_t)t * EMB_D)[lane];
        float p = e2.x * c2.x + e2.y * c2.y;
        #pragma unroll
        for (int o = 16; o; o >>= 1) p += __shfl_xor_sync(0xffffffffu, p, o);
        const float dot = p;

        const int   L    = __ldg(lab + b);
        const float labf = (float)L;

        float taurow = 0.0f;
        int   plabel = KTH + 1;
        float tj[KTH];
        #pragma unroll
        for (int j = KTH - 1; j >= 0; j--) {
            const float db = dot - s_bias[j];
            if (db <= 0.0f) plabel = j + 1;
            const float yt  = (j < L) ? 1.0f : -1.0f;
            const float tau = (db * yt > 0.0f) ? 0.0f : labf;
            tj[j] = tau;
            taurow += tau;
        }
        if (lane == 0) {
            b0 += tj[0]; b1 += tj[1]; b2 += tj[2]; b3 += tj[3];
            if (plabel == L) corr++;
        }
        wx += taurow * e2.x;
        wy += taurow * e2.y;
    }

    s_w[warp][2 * lane]     = wx;
    s_w[warp][2 * lane + 1] = wy;
    if (lane == 0) {
        s_b[warp][0] = b0; s_b[warp][1] = b1; s_b[warp][2] = b2; s_b[warp][3] = b3;
        s_c[warp] = corr;
    }
    __syncthreads();

    if (tid < EMB_D) {
        float s = 0.0f;
        #pragma unroll
        for (int w = 0; w < 8; w++) s += s_w[w][tid];
        g_pw[blockIdx.x][tid] = s;
    }
    if (tid < KTH) {
        float s = 0.0f;
        #pragma unroll
        for (int w = 0; w < 8; w++) s += s_b[w][tid];
        g_pb[blockIdx.x][tid] = s;
    }
    if (tid == 0) {
        int s = 0;
        #pragma unroll
        for (int w = 0; w < 8; w++) s += s_c[w];
        g_pc[blockIdx.x] = s;
    }
}

// ---------------------------------------------------------------------------
// Patch body (run by LAST reduce block, concurrent with copy; writes only the
// 68 patched elements + acc + head + tail, all disjoint from copy stores).
// ---------------------------------------------------------------------------
__device__ void patch_body(const float* __restrict__ emb,
                           const float* __restrict__ bia,
                           const int*   __restrict__ ctx_id,
                           float* __restrict__ out) {
    __shared__ float t_w[4][EMB_D];
    __shared__ float s_w[EMB_D];
    __shared__ float s_pb[4][KTH];
    __shared__ int   s_pc[4];
    __shared__ float s_b[KTH];
    __shared__ int   s_c;

    const int tid  = threadIdx.x;
    const int lane = tid & 31;
    const int warp = tid >> 5;

    // g_pw: 128x64. Group g = tid>>6 accumulates rows g, g+4, ... (coalesced).
    {
        const int g = tid >> 6;
        const int c = tid & 63;
        float acc = 0.0f;
        #pragma unroll
        for (int i = 0; i < RB / 4; i++)
            acc += g_pw[g + 4 * i][c];
        t_w[g][c] = acc;
    }

    // g_pb rows as float4 + shuffle reduce; g_pc alongside.
    if (tid < 128) {
        float4 v = reinterpret_cast<const float4*>(g_pb)[tid];
        int c = g_pc[tid];
        #pragma unroll
        for (int o = 16; o; o >>= 1) {
            v.x += __shfl_xor_sync(0xffffffffu, v.x, o);
            v.y += __shfl_xor_sync(0xffffffffu, v.y, o);
            v.z += __shfl_xor_sync(0xffffffffu, v.z, o);
            v.w += __shfl_xor_sync(0xffffffffu, v.w, o);
            c   += __shfl_xor_sync(0xffffffffu, c, o);
        }
        if (lane == 0) {
            s_pb[warp][0] = v.x; s_pb[warp][1] = v.y;
            s_pb[warp][2] = v.z; s_pb[warp][3] = v.w;
            s_pc[warp] = c;
        }
    }
    __syncthreads();

    if (tid < EMB_D)
        s_w[tid] = t_w[0][tid] + t_w[1][tid] + t_w[2][tid] + t_w[3][tid];
    if (tid >= 64 && tid < 64 + KTH) {
        const int j = tid - 64;
        s_b[j] = s_pb[0][j] + s_pb[1][j] + s_pb[2][j] + s_pb[3][j];
    }
    if (tid == 128)
        s_c = s_pc[0] + s_pc[1] + s_pc[2] + s_pc[3];
    __syncthreads();

    const int  ctx   = __ldg(ctx_id);
    const long wbase = (long)ctx * EMB_D;
    const long bbase = E_ELEMS + (long)ctx * KTH;

    if (tid == 128) out[0] = (float)s_c * INVB;

    // Context embed row (covers head out[1..3] if ctx == 0).
    if (tid < EMB_D)
        out[1 + wbase + tid] = __ldg(emb + wbase + tid) + s_w[tid] * INVB;

    // Context bias row (covers tail out[TOT] if ctx == WORDS-1).
    if (tid >= 64 && tid < 64 + KTH) {
        const int j = tid - 64;
        out[1 + bbase + j] = __ldg(bia + (long)ctx * KTH + j) - s_b[j] * INVB;
    }

    // Head out[1..3]: copy never writes chunk 0.
    if (tid >= 129 && tid < 132 && ctx != 0) {
        const int j = tid - 129;
        out[1 + j] = __ldg(emb + j);
    }
    // Tail out[TOT].
    if (tid == 132 && ctx != WORDS - 1)
        out[TOT_ELEMS] = __ldg(bia + B_ELEMS - 1);
}

// ---------------------------------------------------------------------------
// Single fused kernel.
//   blocks < RB: reduce -> fence -> ticket; last reduce block patches (the
//                patch write-set is disjoint from all copy stores, so no
//                global ordering with the copy is needed).
//   all blocks:  shifted streaming copy; chunks overlapping the patched
//                indices store element-wise, skipping patched slots.
// ---------------------------------------------------------------------------
__global__ void __launch_bounds__(TPB)
prank_main_kernel(const float* __restrict__ emb,
                  const float* __restrict__ bia,
                  const int*   __restrict__ ctx_id,
                  const int*   __restrict__ tgt,
                  const int*   __restrict__ lab,
                  float* __restrict__ out) {
    if (blockIdx.x < RB) {
        reduce_body(emb, bia, ctx_id, tgt, lab);

        __shared__ unsigned int s_last;
        __threadfence();                 // publish this block's partials (RB blocks only)
        __syncthreads();
        if (threadIdx.x == 0) {
            const unsigned int old = atomicAdd(&g_ticket, 1u);
            s_last = (old == RB - 1u) ? 1u : 0u;
            if (s_last) g_ticket = 0;    // reset -> graph-replay safe
        }
        __syncthreads();
        if (s_last) {
            __threadfence();             // acquire other reduce blocks' partials
            patch_body(emb, bia, ctx_id, out);
        }
    }

    const long base = (long)blockIdx.x * CPB + 1;
    const int  tid  = threadIdx.x;
    const int  lane = tid & 31;

    long   k[UNROLL];
    float4 B[UNROLL];
    float  prev[UNROLL];

    #pragma unroll
    for (int i = 0; i < UNROLL; i++) {
        long kk = base + (long)i * TPB + tid;
        if (kk >= K_CH) kk = K_CH - 1;            // clamp keeps warp converged
        k[i] = kk;
        B[i] = load_chunk_cs(kk, emb, bia);
    }

    #pragma unroll
    for (int i = 0; i < UNROLL; i++) {
        prev[i] = __shfl_up_sync(0xffffffffu, B[i].w, 1);
        if (lane == 0) prev[i] = load_src(4 * k[i] - 1, emb, bia);
    }

    // Patched output ranges: [wlo, whi) and [blo, bhi).
    const int  ctx = __ldg(ctx_id);
    const long wlo = 1 + (long)ctx * EMB_D;
    const long whi = wlo + EMB_D;
    const long blo = 1 + E_ELEMS + (long)ctx * KTH;
    const long bhi = blo + KTH;

    #pragma unroll
    for (int i = 0; i < UNROLL; i++) {
        const long kk = base + (long)i * TPB + tid;
        if (kk < K_CH) {
            const long s = 4 * kk;
            const bool ov = (s < whi && s + 4 > wlo) || (s < bhi && s + 4 > blo);
            if (!ov) {
                __stcs(reinterpret_cast<float4*>(out) + kk,
                       make_float4(prev[i], B[i].x, B[i].y, B[i].z));
            } else {
                float oo[4] = {prev[i], B[i].x, B[i].y, B[i].z};
                #pragma unroll
                for (int c = 0; c < 4; c++) {
                    const long idx = s + c;
                    const bool patched = (idx >= wlo && idx < whi) ||
                                         (idx >= blo && idx < bhi);
                    if (!patched) out[idx] = oo[c];
                }
            }
        }
    }
}

extern "C" void kernel_launch(void* const* d_in, const int* in_sizes, int n_in,
                              void* d_out, int out_size) {
    const float* in_embed = (const float*)d_in[0];
    const float* in_bias  = (const float*)d_in[1];
    const int*   ctx_id   = (const int*)d_in[2];
    const int*   tgt      = (const int*)d_in[3];
    const int*   lab      = (const int*)d_in[4];
    float* out = (float*)d_out;
    (void)n_in; (void)out_size; (void)in_sizes;

    const long nchunks = K_CH - 1;                       // chunks 1..K_CH-1
    const int  blocks  = (int)((nchunks + CPB - 1) / CPB);
    prank_main_kernel<<<blocks, TPB>>>(in_embed, in_bias, ctx_id, tgt, lab, out);
}